// round 8
// baseline (speedup 1.0000x reference)
#include <cuda_runtime.h>
#include <cuda_fp16.h>
#include <cstddef>
#include <cstdint>

#define N_NODES 50000
#define N_EDGES 1600000
#define INDIM   256
#define HIDIM   128
#define OUTDIM  64
#define NB_SCAN ((N_NODES + 256) / 256)   // 196
#define NCHUNK  (N_NODES / 2)             // 25000

// ---------------- scratch (allocation-free: __device__ globals) ----------------
__device__ int            g_degi  [N_NODES];
__device__ unsigned short g_pos   [N_EDGES];   // slot within dst bucket (deg < 65536)
__device__ int            g_rowptr[N_NODES + 1];
__device__ int            g_csr   [N_EDGES];
__device__ unsigned long long g_desc[NB_SCAN];
__device__ float  g_dinv  [N_NODES];
__device__ __half g_wt1   [(size_t)HIDIM * INDIM];     // W1^T fp16 [128][256]
__device__ __half g_wt2   [(size_t)OUTDIM * HIDIM];    // W2^T fp16 [64][128]
__device__ __half g_u1h   [(size_t)N_NODES * HIDIM];   // x @ W1 (fp16)
__device__ __half g_h     [(size_t)N_NODES * HIDIM];   // layer1 out (fp16)
__device__ __half g_u2h   [(size_t)N_NODES * OUTDIM];  // h @ W2 (fp16)

// ---------------- CSR build kernels ----------------
__global__ void zero2(int* degi, unsigned long long* desc) {
    int i = blockIdx.x * blockDim.x + threadIdx.x;
    if (i < N_NODES) degi[i] = 0;
    if (i < NB_SCAN) desc[i] = 0ULL;
}

// degree count + per-edge bucket slot (atomic return), 4 edges/thread
__global__ void deg_pos4(const int4* __restrict__ col4, int* __restrict__ degi,
                         ushort4* __restrict__ pos4) {
    int i = blockIdx.x * blockDim.x + threadIdx.x;
    if (i >= N_EDGES / 4) return;
    int4 c = col4[i];
    ushort4 p;
    p.x = (unsigned short)atomicAdd(&degi[c.x], 1);
    p.y = (unsigned short)atomicAdd(&degi[c.y], 1);
    p.z = (unsigned short)atomicAdd(&degi[c.z], 1);
    p.w = (unsigned short)atomicAdd(&degi[c.w], 1);
    pos4[i] = p;
}

// single-pass scan with PARALLEL lookback; also writes dinv.
__global__ void scan_rowptr(const int* __restrict__ degi, float* __restrict__ dinv,
                            int* __restrict__ rowptr,
                            volatile unsigned long long* desc)
{
    __shared__ int sh[256];
    __shared__ int red[256];
    const int b = blockIdx.x, t = threadIdx.x;
    const int i = b * 256 + t;

    int v = (i < N_NODES) ? degi[i] : 0;
    if (i < N_NODES) dinv[i] = rsqrtf((float)v + 1.0f);   // +1 self loop

    sh[t] = v;
    __syncthreads();
    #pragma unroll
    for (int off = 1; off < 256; off <<= 1) {
        int x = (t >= off) ? sh[t - off] : 0;
        __syncthreads();
        sh[t] += x;
        __syncthreads();
    }
    const int incl  = sh[t];
    const int total = sh[255];

    if (t == 0) desc[b] = (1ULL << 32) | (unsigned)total;

    int contrib = 0;
    if (t < b) {
        unsigned long long d;
        do { d = desc[t]; } while ((d >> 32) == 0ULL);
        contrib = (int)(unsigned)d;
    }
    red[t] = contrib;
    __syncthreads();
    #pragma unroll
    for (int s = 128; s > 0; s >>= 1) {
        if (t < s) red[t] += red[t + s];
        __syncthreads();
    }
    const int off = red[0];

    if (i <= N_NODES) rowptr[i] = off + incl - v;
}

// atomic-free fill: csr[rowptr[col] + pos] = row
__global__ void csr_fill4(const int4* __restrict__ row4, const int4* __restrict__ col4,
                          const ushort4* __restrict__ pos4,
                          const int* __restrict__ rowptr, int* __restrict__ csr) {
    int i = blockIdx.x * blockDim.x + threadIdx.x;
    if (i >= N_EDGES / 4) return;
    int4 r = row4[i];
    int4 c = col4[i];
    ushort4 p = pos4[i];
    int b0 = __ldg(&rowptr[c.x]);
    int b1 = __ldg(&rowptr[c.y]);
    int b2 = __ldg(&rowptr[c.z]);
    int b3 = __ldg(&rowptr[c.w]);
    csr[b0 + p.x] = r.x;
    csr[b1 + p.y] = r.y;
    csr[b2 + p.z] = r.z;
    csr[b3 + p.w] = r.w;
}

// ---------------- weight transpose/convert: W [K][M] fp32 -> Wt [M][K] fp16 ----
__global__ void conv_wt(const float* __restrict__ W, __half* __restrict__ Wt, int K, int M) {
    int o = blockIdx.x * blockDim.x + threadIdx.x;
    if (o >= K * M) return;
    int m = o / K, k = o % K;
    Wt[o] = __float2half(W[(size_t)k * M + m]);
}

// ---------------- tensor-core fp16 GEMM: out = A @ Bt^T ----------------
__device__ __forceinline__ void mma16816(float* c, const unsigned* a,
                                         unsigned b0, unsigned b1) {
    asm volatile(
        "mma.sync.aligned.m16n8k16.row.col.f32.f16.f16.f32 "
        "{%0,%1,%2,%3}, {%4,%5,%6,%7}, {%8,%9}, {%0,%1,%2,%3};"
        : "+f"(c[0]), "+f"(c[1]), "+f"(c[2]), "+f"(c[3])
        : "r"(a[0]), "r"(a[1]), "r"(a[2]), "r"(a[3]), "r"(b0), "r"(b1));
}

template <int K, int BN, bool AF32>
__global__ void __launch_bounds__(256)
gemm_mma(const void* __restrict__ Av, const __half* __restrict__ Bt,
         __half* __restrict__ out, int n)
{
    constexpr int BM  = 128;
    constexpr int BK  = 32;
    constexpr int PAD = 40;
    constexpr int WN  = BN / 2;
    constexpr int NT  = WN / 8;
    constexpr int AL  = (BM * 8) / 256;
    constexpr int BL  = (BN * 8) / 256;

    __shared__ __half As[2][BM][PAD];
    __shared__ __half Bs[2][BN][PAD];

    const int tid  = threadIdx.x;
    const int lane = tid & 31;
    const int wid  = tid >> 5;
    const int wr   = wid & 3;
    const int wc   = wid >> 2;
    const int rowBase = blockIdx.x * BM;

    const int r4 = lane >> 2;
    const int c2 = (lane & 3) * 2;

    float acc[2][NT][4];
    #pragma unroll
    for (int mt = 0; mt < 2; mt++)
        #pragma unroll
        for (int nt = 0; nt < NT; nt++)
            #pragma unroll
            for (int q = 0; q < 4; q++) acc[mt][nt][q] = 0.f;

    uint2 abuf[AL], bbuf[BL];

    auto loadA = [&](int k0) {
        #pragma unroll
        for (int i = 0; i < AL; i++) {
            int idx = tid + i * 256;
            int r = idx >> 3, sg = idx & 7;
            int gr = rowBase + r;
            uint2 v = make_uint2(0u, 0u);
            if (gr < n) {
                if (AF32) {
                    float4 f = *reinterpret_cast<const float4*>(
                        (const float*)Av + (size_t)gr * K + k0 + sg * 4);
                    __half2 h0 = __floats2half2_rn(f.x, f.y);
                    __half2 h1 = __floats2half2_rn(f.z, f.w);
                    v.x = *reinterpret_cast<unsigned*>(&h0);
                    v.y = *reinterpret_cast<unsigned*>(&h1);
                } else {
                    v = *reinterpret_cast<const uint2*>(
                        (const __half*)Av + (size_t)gr * K + k0 + sg * 4);
                }
            }
            abuf[i] = v;
        }
    };
    auto loadB = [&](int k0) {
        #pragma unroll
        for (int i = 0; i < BL; i++) {
            int idx = tid + i * 256;
            int r = idx >> 3, sg = idx & 7;
            bbuf[i] = *reinterpret_cast<const uint2*>(&Bt[(size_t)r * K + k0 + sg * 4]);
        }
    };
    auto store = [&](int s) {
        #pragma unroll
        for (int i = 0; i < AL; i++) {
            int idx = tid + i * 256;
            int r = idx >> 3, sg = idx & 7;
            *reinterpret_cast<uint2*>(&As[s][r][sg * 4]) = abuf[i];
        }
        #pragma unroll
        for (int i = 0; i < BL; i++) {
            int idx = tid + i * 256;
            int r = idx >> 3, sg = idx & 7;
            *reinterpret_cast<uint2*>(&Bs[s][r][sg * 4]) = bbuf[i];
        }
    };

    loadA(0); loadB(0);
    store(0);
    __syncthreads();

    constexpr int NSTEP = K / BK;
    #pragma unroll
    for (int step = 0; step < NSTEP; step++) {
        const int s = step & 1;
        if (step + 1 < NSTEP) { loadA((step + 1) * BK); loadB((step + 1) * BK); }

        #pragma unroll
        for (int ks = 0; ks < BK; ks += 16) {
            unsigned a[2][4];
            #pragma unroll
            for (int mt = 0; mt < 2; mt++) {
                int m0 = wr * 32 + mt * 16;
                a[mt][0] = *reinterpret_cast<const unsigned*>(&As[s][m0 + r4    ][ks + c2    ]);
                a[mt][1] = *reinterpret_cast<const unsigned*>(&As[s][m0 + r4 + 8][ks + c2    ]);
                a[mt][2] = *reinterpret_cast<const unsigned*>(&As[s][m0 + r4    ][ks + c2 + 8]);
                a[mt][3] = *reinterpret_cast<const unsigned*>(&As[s][m0 + r4 + 8][ks + c2 + 8]);
            }
            #pragma unroll
            for (int nt = 0; nt < NT; nt++) {
                int n0 = wc * WN + nt * 8;
                unsigned b0 = *reinterpret_cast<const unsigned*>(&Bs[s][n0 + r4][ks + c2    ]);
                unsigned b1 = *reinterpret_cast<const unsigned*>(&Bs[s][n0 + r4][ks + c2 + 8]);
                mma16816(acc[0][nt], a[0], b0, b1);
                mma16816(acc[1][nt], a[1], b0, b1);
            }
        }
        __syncthreads();
        if (step + 1 < NSTEP) {
            store(s ^ 1);
            __syncthreads();
        }
    }

    #pragma unroll
    for (int mt = 0; mt < 2; mt++) {
        #pragma unroll
        for (int nt = 0; nt < NT; nt++) {
            int row0 = rowBase + wr * 32 + mt * 16 + r4;
            int col  = wc * WN + nt * 8 + c2;
            if (row0 < n) {
                __half2 h = __floats2half2_rn(acc[mt][nt][0], acc[mt][nt][1]);
                *reinterpret_cast<unsigned*>(&out[(size_t)row0 * BN + col]) =
                    *reinterpret_cast<unsigned*>(&h);
            }
            if (row0 + 8 < n) {
                __half2 h = __floats2half2_rn(acc[mt][nt][2], acc[mt][nt][3]);
                *reinterpret_cast<unsigned*>(&out[(size_t)(row0 + 8) * BN + col]) =
                    *reinterpret_cast<unsigned*>(&h);
            }
        }
    }
}

// ---------------- CSR gather-aggregate over fp16 messages ----------------
__device__ __forceinline__ void acc_half4(float4& acc, float w, uint2 raw) {
    __half2 p0 = *reinterpret_cast<__half2*>(&raw.x);
    __half2 p1 = *reinterpret_cast<__half2*>(&raw.y);
    float2 f0 = __half22float2(p0);
    float2 f1 = __half22float2(p1);
    acc.x = fmaf(w, f0.x, acc.x);
    acc.y = fmaf(w, f0.y, acc.y);
    acc.z = fmaf(w, f1.x, acc.z);
    acc.w = fmaf(w, f1.y, acc.w);
}

// out[c] = [relu]( dinv[c] * ( sum_{r in N(c)} dinv[r]*u[r] + dinv[c]*u[c] ) + b )
// Processes nodes [nodeBase, nodeBase + span). 8-deep gather MLP.
template <int L, bool RELU, bool HOUT>
__global__ void aggregate_h(const int* __restrict__ rowptr, const int* __restrict__ csr,
                            const __half* __restrict__ Gh, const float* __restrict__ dinv,
                            const float4* __restrict__ bias, void* __restrict__ outv,
                            int nodeBase)
{
    constexpr int RS = L * 4;
    const int node = nodeBase + (blockIdx.x * blockDim.x + threadIdx.x) / L;
    const int lane = threadIdx.x % L;

    const float ds = dinv[node];
    float4 acc = make_float4(0.f, 0.f, 0.f, 0.f);
    {
        uint2 raw = *reinterpret_cast<const uint2*>(&Gh[(size_t)node * RS + lane * 4]);
        acc_half4(acc, ds, raw);
    }

    const int start = rowptr[node];
    const int end   = rowptr[node + 1];

    int idx = 0; float dd = 0.f;
    if (start + lane < end) { int t = csr[start + lane]; idx = t; dd = dinv[t]; }

    for (int p = start; p < end; p += L) {
        const int m = min(L, end - p);
        int nidx = 0; float ndd = 0.f;
        if (p + L < end && p + L + lane < end) {
            int t = csr[p + L + lane]; nidx = t; ndd = dinv[t];
        }

        int j = 0;
        for (; j + 8 <= m; j += 8) {
            int r[8]; float w[8]; uint2 v[8];
            #pragma unroll
            for (int q = 0; q < 8; q++) {
                r[q] = __shfl_sync(0xffffffffu, idx, j + q, L);
                w[q] = __shfl_sync(0xffffffffu, dd,  j + q, L);
            }
            #pragma unroll
            for (int q = 0; q < 8; q++)
                v[q] = *reinterpret_cast<const uint2*>(&Gh[(size_t)r[q] * RS + lane * 4]);
            #pragma unroll
            for (int q = 0; q < 8; q++)
                acc_half4(acc, w[q], v[q]);
        }
        for (; j + 4 <= m; j += 4) {
            int r[4]; float w[4]; uint2 v[4];
            #pragma unroll
            for (int q = 0; q < 4; q++) {
                r[q] = __shfl_sync(0xffffffffu, idx, j + q, L);
                w[q] = __shfl_sync(0xffffffffu, dd,  j + q, L);
            }
            #pragma unroll
            for (int q = 0; q < 4; q++)
                v[q] = *reinterpret_cast<const uint2*>(&Gh[(size_t)r[q] * RS + lane * 4]);
            #pragma unroll
            for (int q = 0; q < 4; q++)
                acc_half4(acc, w[q], v[q]);
        }
        for (; j < m; j++) {
            int   r = __shfl_sync(0xffffffffu, idx, j, L);
            float w = __shfl_sync(0xffffffffu, dd,  j, L);
            uint2 a = *reinterpret_cast<const uint2*>(&Gh[(size_t)r * RS + lane * 4]);
            acc_half4(acc, w, a);
        }
        idx = nidx; dd = ndd;
    }

    float4 bb = bias[lane];
    float4 r;
    r.x = fmaf(ds, acc.x, bb.x);
    r.y = fmaf(ds, acc.y, bb.y);
    r.z = fmaf(ds, acc.z, bb.z);
    r.w = fmaf(ds, acc.w, bb.w);
    if (RELU) {
        r.x = fmaxf(r.x, 0.f); r.y = fmaxf(r.y, 0.f);
        r.z = fmaxf(r.z, 0.f); r.w = fmaxf(r.w, 0.f);
    }
    if (HOUT) {
        __half2 h0 = __floats2half2_rn(r.x, r.y);
        __half2 h1 = __floats2half2_rn(r.z, r.w);
        uint2 o;
        o.x = *reinterpret_cast<unsigned*>(&h0);
        o.y = *reinterpret_cast<unsigned*>(&h1);
        reinterpret_cast<uint2*>(outv)[(size_t)node * L + lane] = o;
    } else {
        reinterpret_cast<float4*>(outv)[(size_t)node * L + lane] = r;
    }
}

// ---------------- launch ----------------
extern "C" void kernel_launch(void* const* d_in, const int* in_sizes, int n_in,
                              void* d_out, int out_size)
{
    const float* x  = (const float*)d_in[0];
    const int*   ei = (const int*)  d_in[1];
    const float* W1 = (const float*)d_in[2];
    const float* b1 = (const float*)d_in[3];
    const float* W2 = (const float*)d_in[4];
    const float* b2 = (const float*)d_in[5];
    float* out = (float*)d_out;

    int *degi, *rowptr, *csr;
    unsigned short* pos;
    unsigned long long* desc;
    float *dinv;
    __half *wt1, *wt2, *u1h, *h, *u2h;
    cudaGetSymbolAddress((void**)&degi,   g_degi);
    cudaGetSymbolAddress((void**)&pos,    g_pos);
    cudaGetSymbolAddress((void**)&rowptr, g_rowptr);
    cudaGetSymbolAddress((void**)&csr,    g_csr);
    cudaGetSymbolAddress((void**)&desc,   g_desc);
    cudaGetSymbolAddress((void**)&dinv,   g_dinv);
    cudaGetSymbolAddress((void**)&wt1,    g_wt1);
    cudaGetSymbolAddress((void**)&wt2,    g_wt2);
    cudaGetSymbolAddress((void**)&u1h,    g_u1h);
    cudaGetSymbolAddress((void**)&h,      g_h);
    cudaGetSymbolAddress((void**)&u2h,    g_u2h);

    static cudaStream_t s1 = nullptr;
    static cudaEvent_t  evFork = nullptr, evJoin = nullptr, evA0 = nullptr, evG0 = nullptr;
    if (!s1) {
        cudaStreamCreateWithFlags(&s1, cudaStreamNonBlocking);
        cudaEventCreateWithFlags(&evFork, cudaEventDisableTiming);
        cudaEventCreateWithFlags(&evJoin, cudaEventDisableTiming);
        cudaEventCreateWithFlags(&evA0,   cudaEventDisableTiming);
        cudaEventCreateWithFlags(&evG0,   cudaEventDisableTiming);
    }

    const int T = 256;

    // ---- fork: CSR build chain + W2 convert on s1 ----
    cudaEventRecord(evFork, 0);
    cudaStreamWaitEvent(s1, evFork, 0);

    zero2    <<<(N_NODES + T - 1) / T, T, 0, s1>>>(degi, desc);
    deg_pos4 <<<(N_EDGES / 4 + T - 1) / T, T, 0, s1>>>(
        (const int4*)(ei + N_EDGES), degi, (ushort4*)pos);
    scan_rowptr<<<NB_SCAN, 256, 0, s1>>>(degi, dinv, rowptr, desc);
    csr_fill4<<<(N_EDGES / 4 + T - 1) / T, T, 0, s1>>>(
        (const int4*)ei, (const int4*)(ei + N_EDGES), (const ushort4*)pos,
        rowptr, csr);
    conv_wt<<<(HIDIM * OUTDIM + T - 1) / T, T, 0, s1>>>(W2, wt2, HIDIM, OUTDIM);

    // ---- main stream: W1 convert + GEMM1 (x converted inside tile load) ----
    conv_wt<<<(INDIM * HIDIM + T - 1) / T, T>>>(W1, wt1, INDIM, HIDIM);
    gemm_mma<INDIM, HIDIM, true>
        <<<(N_NODES + 127) / 128, 256>>>((const void*)x, wt1, u1h, N_NODES);

    // ---- join ----
    cudaEventRecord(evJoin, s1);
    cudaStreamWaitEvent(0, evJoin, 0);

    // ---- layer 1 aggregate, chunked; GEMM2(chunk0) overlaps agg1(chunk1) ----
    aggregate_h<32, true, true><<<NCHUNK / 8, 256>>>(
        rowptr, csr, u1h, dinv, (const float4*)b1, (void*)h, 0);
    cudaEventRecord(evA0, 0);

    cudaStreamWaitEvent(s1, evA0, 0);
    gemm_mma<HIDIM, OUTDIM, false>
        <<<(NCHUNK + 127) / 128, 256, 0, s1>>>((const void*)h, wt2, u2h, NCHUNK);
    cudaEventRecord(evG0, s1);

    aggregate_h<32, true, true><<<NCHUNK / 8, 256>>>(
        rowptr, csr, u1h, dinv, (const float4*)b1, (void*)h, NCHUNK);
    gemm_mma<HIDIM, OUTDIM, false>
        <<<(NCHUNK + 127) / 128, 256>>>(
            (const void*)(h + (size_t)NCHUNK * HIDIM), wt2,
            u2h + (size_t)NCHUNK * OUTDIM, NCHUNK);

    cudaStreamWaitEvent(0, evG0, 0);

    // ---- layer 2 aggregate ----
    aggregate_h<16, false, false><<<N_NODES / 16, 256>>>(
        rowptr, csr, u2h, dinv, (const float4*)b2, (void*)out, 0);
}